// round 15
// baseline (speedup 1.0000x reference)
#include <cuda_runtime.h>
#include <cuda_fp16.h>
#include <math.h>
#include <stdint.h>

#define N_TOKEN 16384
#define DMODEL  4096
#define NEXP    16
#define NSEL    4
#define M_TILE  64
#define NBLOCKS (N_TOKEN / M_TILE)   // 256
#define NTHREADS 128
#define KC      64                   // K elements per chunk
#define NCHUNK  (DMODEL / KC)        // 64
#define HS 33

// B fragments in MMA layout: [ksg(256)][nt(4)][lane(32)] x uint2{b0,b1}
__device__ uint2 g_wfh[256 * 4 * 32];
__device__ uint2 g_wfl[256 * 4 * 32];
__device__ float g_imp[NEXP];
__device__ float g_load[NEXP];
__device__ unsigned g_count;

#define MMA_F16(d, a, b0, b1) \
    asm volatile("mma.sync.aligned.m16n8k16.row.col.f32.f16.f16.f32 " \
        "{%0,%1,%2,%3},{%4,%5,%6,%7},{%8,%9},{%0,%1,%2,%3};" \
        : "+f"(d[0]), "+f"(d[1]), "+f"(d[2]), "+f"(d[3]) \
        : "r"(a[0]), "r"(a[1]), "r"(a[2]), "r"(a[3]), "r"(b0), "r"(b1))

// 2-way fp16 split of an fp32 pair: v ~= h + l (to ~2^-23 relative)
__device__ __forceinline__ void split2h(float2 v, uint32_t& h, uint32_t& l) {
    __half2 hv = __float22half2_rn(v);          // lo = v.x, hi = v.y
    float2 hf = __half22float2(hv);
    __half2 lv = __float22half2_rn(make_float2(v.x - hf.x, v.y - hf.y));
    h = *reinterpret_cast<uint32_t*>(&hv);
    l = *reinterpret_cast<uint32_t*>(&lv);
}

__device__ __forceinline__ uint32_t packh(float a, float b) {
    __half2 p = __halves2half2(__float2half_rn(a), __float2half_rn(b));
    return *reinterpret_cast<uint32_t*>(&p);
}

// one-shot: split w1||wn to fp16 hi/lo, laid out as MMA B fragments
__global__ void wsplit_kernel(const float* __restrict__ w1,
                              const float* __restrict__ wn)
{
    int i = blockIdx.x * blockDim.x + threadIdx.x;   // 0 .. 32767
    int lane = i & 31;
    int nt   = (i >> 5) & 3;
    int ksg  = i >> 7;                // global kstep 0..255
    int group = lane >> 2, tg = lane & 3;
    int n = nt * 8 + group;           // expert row 0..31
    const float* wr = (n < NEXP) ? (w1 + (size_t)n * DMODEL)
                                 : (wn + (size_t)(n - NEXP) * DMODEL);
    int k0 = ksg * 16 + tg * 2;
    float v0 = wr[k0],     v1 = wr[k0 + 1];
    float v2 = wr[k0 + 8], v3 = wr[k0 + 9];
    float h0 = __half2float(__float2half_rn(v0));
    float h1 = __half2float(__float2half_rn(v1));
    float h2 = __half2float(__float2half_rn(v2));
    float h3 = __half2float(__float2half_rn(v3));
    g_wfh[i] = make_uint2(packh(v0, v1), packh(v2, v3));
    g_wfl[i] = make_uint2(packh(v0 - h0, v1 - h1), packh(v2 - h2, v3 - h3));
}

__global__ __launch_bounds__(NTHREADS, 4)
void gate_kernel(const float* __restrict__ x,
                 const float* __restrict__ w2,
                 const float* __restrict__ noise,
                 float* __restrict__ out)
{
    __shared__ float hsum[M_TILE * HS];
    __shared__ float w2_s[NEXP * NEXP];
    __shared__ float imp_s[NEXP];
    __shared__ float load_s[NEXP];
    __shared__ int s_last;

    const int tid  = threadIdx.x;
    const int warp = tid >> 5;       // m16 tile 0..3
    const int lane = tid & 31;
    const int group = lane >> 2;
    const int tg = lane & 3;
    const int tok0 = blockIdx.x * M_TILE;
    const int arow0 = warp * 16 + group;

    w2_s[tid] = w2[tid];
    w2_s[tid + 128] = w2[tid + 128];
    if (tid < NEXP) { imp_s[tid] = 0.f; load_s[tid] = 0.f; }

    // per-thread global row base pointers (constant across k)
    const float* p0 = x + (size_t)(tok0 + arow0) * DMODEL + tg * 2;
    const float* p1 = p0 + (size_t)8 * DMODEL;

    // dH: hh (drained every 2 chunks into IEEE fp32 mst); dM: xl*wh; dL: xh*wl
    float dH[4][4], dM[4][4], dL[4][4], mst[4][4];
#pragma unroll
    for (int nt = 0; nt < 4; nt++)
#pragma unroll
        for (int q = 0; q < 4; q++) {
            dH[nt][q] = 0.f; dM[nt][q] = 0.f; dL[nt][q] = 0.f; mst[nt][q] = 0.f;
        }

    for (int c = 0; c < NCHUNK; c++) {
        const int kc = c * KC;
#pragma unroll
        for (int s = 0; s < 4; s++) {
            const int k0 = kc + s * 16;
            // A fragments straight from global (coalesced LDG.64 per quad)
            float2 va00 = *(const float2*)(p0 + k0);
            float2 va10 = *(const float2*)(p1 + k0);
            float2 va01 = *(const float2*)(p0 + k0 + 8);
            float2 va11 = *(const float2*)(p1 + k0 + 8);
            // B fragments straight from packed arrays (L2-resident, coalesced)
            const int ksg = c * 4 + s;
            uint2 bh0 = g_wfh[(ksg * 4 + 0) * 32 + lane];
            uint2 bh1 = g_wfh[(ksg * 4 + 1) * 32 + lane];
            uint2 bh2 = g_wfh[(ksg * 4 + 2) * 32 + lane];
            uint2 bh3 = g_wfh[(ksg * 4 + 3) * 32 + lane];
            uint2 bl0 = g_wfl[(ksg * 4 + 0) * 32 + lane];
            uint2 bl1 = g_wfl[(ksg * 4 + 1) * 32 + lane];
            uint2 bl2 = g_wfl[(ksg * 4 + 2) * 32 + lane];
            uint2 bl3 = g_wfl[(ksg * 4 + 3) * 32 + lane];

            uint32_t ah[4], al[4];
            split2h(va00, ah[0], al[0]);
            split2h(va10, ah[1], al[1]);
            split2h(va01, ah[2], al[2]);
            split2h(va11, ah[3], al[3]);

            MMA_F16(dH[0], ah, bh0.x, bh0.y);
            MMA_F16(dH[1], ah, bh1.x, bh1.y);
            MMA_F16(dH[2], ah, bh2.x, bh2.y);
            MMA_F16(dH[3], ah, bh3.x, bh3.y);
            MMA_F16(dM[0], al, bh0.x, bh0.y);
            MMA_F16(dM[1], al, bh1.x, bh1.y);
            MMA_F16(dM[2], al, bh2.x, bh2.y);
            MMA_F16(dM[3], al, bh3.x, bh3.y);
            MMA_F16(dL[0], ah, bl0.x, bl0.y);
            MMA_F16(dL[1], ah, bl1.x, bl1.y);
            MMA_F16(dL[2], ah, bl2.x, bl2.y);
            MMA_F16(dL[3], ah, bl3.x, bl3.y);
        }

        // drain hh chain into IEEE fp32 master every 2 chunks
        if ((c & 1) == 1) {
#pragma unroll
            for (int nt = 0; nt < 4; nt++)
#pragma unroll
                for (int q = 0; q < 4; q++) { mst[nt][q] += dH[nt][q]; dH[nt][q] = 0.f; }
        }
    }

    // ---- D -> hsum ----
#pragma unroll
    for (int nt = 0; nt < 4; nt++) {
        int col = nt * 8 + tg * 2;
#pragma unroll
        for (int q = 0; q < 4; q++) {
            float v = mst[nt][q] + dH[nt][q] + (dM[nt][q] + dL[nt][q]);
            int row = (q < 2) ? arow0 : arow0 + 8;
            hsum[row * HS + col + (q & 1)] = v;
        }
    }
    __syncthreads();

    // ---- epilogue: one thread per token (128 threads < 64? no: 64 of 128) ----
    if (tid < M_TILE) {
        const int t = tid;
        const int tok = tok0 + t;
        float g[NEXP], ctrl[NEXP], lg[NEXP], ln[NEXP], lo[NEXP];
#pragma unroll
        for (int e = 0; e < NEXP; e++) g[e] = tanhf(hsum[t * HS + e]);
#pragma unroll
        for (int e = 0; e < NEXP; e++) {
            float v = hsum[t * HS + NEXP + e];
            float sp = (v > 20.f) ? v : log1pf(__expf(v));
            ctrl[e] = sp + 0.01f;   // NOISE_EPS
        }
#pragma unroll
        for (int f = 0; f < NEXP; f++) {
            float s = 0.f;
#pragma unroll
            for (int e = 0; e < NEXP; e++) s = fmaf(g[e], w2_s[f * NEXP + e], s);
            lg[f] = s;
        }
        const float4* np = (const float4*)(noise + (size_t)tok * NEXP);
        float4 nz0 = np[0], nz1 = np[1], nz2 = np[2], nz3 = np[3];
        float nf[NEXP] = {nz0.x, nz0.y, nz0.z, nz0.w, nz1.x, nz1.y, nz1.z, nz1.w,
                          nz2.x, nz2.y, nz2.z, nz2.w, nz3.x, nz3.y, nz3.z, nz3.w};
#pragma unroll
        for (int f = 0; f < NEXP; f++) {
            ln[f] = nf[f] * ctrl[f];
            lo[f] = lg[f] + ln[f];
        }

        // top-5 (stable: ties keep smaller index)
        float tv[5]; int tix[5]; unsigned used = 0;
#pragma unroll
        for (int p = 0; p < 5; p++) {
            float best = -1e30f; int bi = 0;
#pragma unroll
            for (int f = 0; f < NEXP; f++) {
                bool ok = !((used >> f) & 1u) && (lo[f] > best);
                best = ok ? lo[f] : best;
                bi   = ok ? f     : bi;
            }
            used |= 1u << bi;
            tv[p] = best; tix[p] = bi;
        }

        float ex[NSEL], ssum = 0.f;
#pragma unroll
        for (int p = 0; p < NSEL; p++) { ex[p] = __expf(tv[p] - tv[0]); ssum += ex[p]; }
        float inv = 1.f / ssum;
#pragma unroll
        for (int p = 0; p < NSEL; p++) {
            float sc = ex[p] * inv;
            out[(size_t)tok * NSEL + p] = (float)tix[p];
            out[(size_t)N_TOKEN * NSEL + (size_t)tok * NSEL + p] = sc;
            atomicAdd(&imp_s[tix[p]], sc);
        }
        const float thr_in  = tv[4];
        const float thr_out = tv[3];
#pragma unroll
        for (int f = 0; f < NEXP; f++) {
            float thr = (ln[f] > thr_in) ? thr_in : thr_out;
            atomicAdd(&load_s[f], normcdff((lg[f] - thr) / ctrl[f]));
        }
    }
    __syncthreads();

    // ---- fused loss: global atomics, last block reduces ----
    if (tid < NEXP) {
        atomicAdd(&g_imp[tid],  imp_s[tid]);
        atomicAdd(&g_load[tid], load_s[tid]);
        __threadfence();
    }
    __syncthreads();
    if (tid == 0) s_last = (atomicAdd(&g_count, 1u) == NBLOCKS - 1);
    __syncthreads();
    if (s_last && tid == 0) {
        volatile float* vi = g_imp;
        volatile float* vl = g_load;
        double si = 0, sqi = 0, sl = 0, sql = 0;
        for (int e = 0; e < NEXP; e++) {
            double a = (double)vi[e]; si += a; sqi += a * a;
            double b = (double)vl[e]; sl += b; sql += b * b;
        }
        double mi = si / NEXP, ml = sl / NEXP;
        double viv = (sqi - si * si / NEXP) / (NEXP - 1);
        double vlv = (sql - sl * sl / NEXP) / (NEXP - 1);
        double cv = viv / (mi * mi + 1e-10) + vlv / (ml * ml + 1e-10);
        out[(size_t)2 * N_TOKEN * NSEL] = (float)(0.01 * cv);
        for (int e = 0; e < NEXP; e++) { g_imp[e] = 0.f; g_load[e] = 0.f; }
        g_count = 0;
    }
}

extern "C" void kernel_launch(void* const* d_in, const int* in_sizes, int n_in,
                              void* d_out, int out_size)
{
    const float* x     = (const float*)d_in[0];
    const float* w1    = (const float*)d_in[1];
    const float* w2    = (const float*)d_in[2];
    const float* wn    = (const float*)d_in[3];
    const float* noise = (const float*)d_in[4];
    float* out = (float*)d_out;

    wsplit_kernel<<<128, 256>>>(w1, wn);
    gate_kernel<<<NBLOCKS, NTHREADS>>>(x, w2, noise, out);
}

// round 16
// speedup vs baseline: 1.5846x; 1.5846x over previous
#include <cuda_runtime.h>
#include <cuda_fp16.h>
#include <math.h>
#include <stdint.h>

#define N_TOKEN 16384
#define DMODEL  4096
#define NEXP    16
#define NSEL    4
#define M_TILE  64
#define NBLOCKS (N_TOKEN / M_TILE)   // 256
#define NTHREADS 128
#define KC      64                   // K elements per chunk
#define NCHUNK  (DMODEL / KC)        // 64
#define KSTEPS  (KC / 16)            // 4

#define XR 68                        // x smem row stride (floats)
#define XBUF (M_TILE * XR)           // 4352 floats = 17408 B per stage
#define WCH  512                     // uint2 fragments per chunk per plane
#define WBUF (2 * WCH)               // hi+lo planes, uint2
#define NSTAGE 4
#define DSMEM (NSTAGE * XBUF * 4 + NSTAGE * WBUF * 8)   // 102400 B
#define HS 33

// B fragments in MMA layout: [ksg(256)][nt(4)][lane(32)] x uint2{b0,b1}
__device__ uint2 g_wfh[256 * 4 * 32];
__device__ uint2 g_wfl[256 * 4 * 32];
__device__ float g_imp[NEXP];
__device__ float g_load[NEXP];
__device__ unsigned g_count;

#define CP_ASYNC16(dst_s, src_g) \
    asm volatile("cp.async.cg.shared.global [%0], [%1], 16;" :: "r"(dst_s), "l"(src_g))
#define CP_COMMIT() asm volatile("cp.async.commit_group;")
#define CP_WAIT2()  asm volatile("cp.async.wait_group 2;")

#define MMA_F16(d, a, b0, b1) \
    asm volatile("mma.sync.aligned.m16n8k16.row.col.f32.f16.f16.f32 " \
        "{%0,%1,%2,%3},{%4,%5,%6,%7},{%8,%9},{%0,%1,%2,%3};" \
        : "+f"(d[0]), "+f"(d[1]), "+f"(d[2]), "+f"(d[3]) \
        : "r"(a[0]), "r"(a[1]), "r"(a[2]), "r"(a[3]), "r"(b0), "r"(b1))

// 2-way fp16 split of an fp32 pair: v ~= h + l (to ~2^-23 relative)
__device__ __forceinline__ void split2h(float2 v, uint32_t& h, uint32_t& l) {
    __half2 hv = __float22half2_rn(v);          // lo = v.x, hi = v.y
    float2 hf = __half22float2(hv);
    __half2 lv = __float22half2_rn(make_float2(v.x - hf.x, v.y - hf.y));
    h = *reinterpret_cast<uint32_t*>(&hv);
    l = *reinterpret_cast<uint32_t*>(&lv);
}

__device__ __forceinline__ uint32_t packh(float a, float b) {
    __half2 p = __halves2half2(__float2half_rn(a), __float2half_rn(b));
    return *reinterpret_cast<uint32_t*>(&p);
}

// one-shot: split w1||wn to fp16 hi/lo, laid out as MMA B fragments
__global__ void wsplit_kernel(const float* __restrict__ w1,
                              const float* __restrict__ wn)
{
    int i = blockIdx.x * blockDim.x + threadIdx.x;   // 0 .. 32767
    int lane = i & 31;
    int nt   = (i >> 5) & 3;
    int ksg  = i >> 7;                // global kstep 0..255
    int group = lane >> 2, tg = lane & 3;
    int n = nt * 8 + group;           // expert row 0..31
    const float* wr = (n < NEXP) ? (w1 + (size_t)n * DMODEL)
                                 : (wn + (size_t)(n - NEXP) * DMODEL);
    int k0 = ksg * 16 + tg * 2;
    float v0 = wr[k0],     v1 = wr[k0 + 1];
    float v2 = wr[k0 + 8], v3 = wr[k0 + 9];
    float h0 = __half2float(__float2half_rn(v0));
    float h1 = __half2float(__float2half_rn(v1));
    float h2 = __half2float(__float2half_rn(v2));
    float h3 = __half2float(__float2half_rn(v3));
    g_wfh[i] = make_uint2(packh(v0, v1), packh(v2, v3));
    g_wfl[i] = make_uint2(packh(v0 - h0, v1 - h1), packh(v2 - h2, v3 - h3));
}

__global__ __launch_bounds__(NTHREADS, 2)
void gate_kernel(const float* __restrict__ x,
                 const float* __restrict__ w2,
                 const float* __restrict__ noise,
                 float* __restrict__ out)
{
    extern __shared__ __align__(16) char dyn[];
    float* x_s = (float*)dyn;
    uint2* wf_s = (uint2*)(dyn + NSTAGE * XBUF * 4);

    __shared__ float w2_s[NEXP * NEXP];
    __shared__ float imp_s[NEXP];
    __shared__ float load_s[NEXP];
    __shared__ int s_last;

    const int tid  = threadIdx.x;
    const int warp = tid >> 5;       // m16 tile 0..3
    const int lane = tid & 31;
    const int group = lane >> 2;
    const int tg = lane & 3;
    const int tok0 = blockIdx.x * M_TILE;
    const int arow0 = warp * 16 + group;

    w2_s[tid] = w2[tid];
    w2_s[tid + 128] = w2[tid + 128];
    if (tid < NEXP) { imp_s[tid] = 0.f; load_s[tid] = 0.f; }

    const int xrow_lo = tid >> 4;    // 0..7
    const int xq = tid & 15;

    auto prefetch = [&](int c) {
        const int st = c & 3;
        float* xb = x_s + st * XBUF;
        uint2* wb = wf_s + st * WBUF;
        const float* xsrc = x + (size_t)tok0 * DMODEL + c * KC;
#pragma unroll
        for (int r = 0; r < 8; r++) {
            int row = r * 8 + xrow_lo;
            uint32_t dst = (uint32_t)__cvta_generic_to_shared(xb + row * XR + xq * 4);
            CP_ASYNC16(dst, xsrc + (size_t)row * DMODEL + xq * 4);
        }
        const char* srch = (const char*)(g_wfh + (size_t)c * WCH);
        const char* srcl = (const char*)(g_wfl + (size_t)c * WCH);
        char* dsth = (char*)wb;
        char* dstl = (char*)(wb + WCH);
#pragma unroll
        for (int r = 0; r < 2; r++) {
            int idx = r * NTHREADS + tid;   // 0..255 float4s per plane
            CP_ASYNC16((uint32_t)__cvta_generic_to_shared(dsth + idx * 16), srch + idx * 16);
            CP_ASYNC16((uint32_t)__cvta_generic_to_shared(dstl + idx * 16), srcl + idx * 16);
        }
        CP_COMMIT();
    };

    prefetch(0); prefetch(1); prefetch(2);

    // dH: hh (drained every 2 chunks into IEEE fp32 mst); dM: xl*wh; dL: xh*wl
    float dH[4][4], dM[4][4], dL[4][4], mst[4][4];
#pragma unroll
    for (int nt = 0; nt < 4; nt++)
#pragma unroll
        for (int q = 0; q < 4; q++) {
            dH[nt][q] = 0.f; dM[nt][q] = 0.f; dL[nt][q] = 0.f; mst[nt][q] = 0.f;
        }

    for (int c = 0; c < NCHUNK; c++) {
        const int st = c & 3;
        CP_WAIT2();            // <=2 groups pending -> group c complete
        __syncthreads();       // stage c visible block-wide

        // prefetch stage (c+3)&3 == (c-1)&3 — consumed at chunk c-1; every
        // warp is past this chunk-c barrier, hence done with c-1's compute.
        if (c + 3 < NCHUNK) prefetch(c + 3);
        else CP_COMMIT();      // keep wait_group counts exact at tail

        const float* xb = x_s + st * XBUF;
        const uint2* wfh = wf_s + st * WBUF;
        const uint2* wfl = wfh + WCH;

#pragma unroll
        for (int s = 0; s < KSTEPS; s++) {
            const int k0 = s * 16;
            float2 va00 = *(const float2*)(xb + arow0 * XR + k0 + tg * 2);
            float2 va10 = *(const float2*)(xb + (arow0 + 8) * XR + k0 + tg * 2);
            float2 va01 = *(const float2*)(xb + arow0 * XR + k0 + tg * 2 + 8);
            float2 va11 = *(const float2*)(xb + (arow0 + 8) * XR + k0 + tg * 2 + 8);
            uint32_t ah[4], al[4];
            split2h(va00, ah[0], al[0]);
            split2h(va10, ah[1], al[1]);
            split2h(va01, ah[2], al[2]);
            split2h(va11, ah[3], al[3]);
#pragma unroll
            for (int nt = 0; nt < 4; nt++) {
                uint2 bh = wfh[(s * 4 + nt) * 32 + lane];
                uint2 bl = wfl[(s * 4 + nt) * 32 + lane];
                MMA_F16(dH[nt], ah, bh.x, bh.y);   // h*h  (2^0)
                MMA_F16(dM[nt], al, bh.x, bh.y);   // l*h  (2^-12)
                MMA_F16(dL[nt], ah, bl.x, bl.y);   // h*l  (2^-12)
            }
        }

        // drain hh chain into IEEE fp32 master every 2 chunks
        if ((c & 1) == 1) {
#pragma unroll
            for (int nt = 0; nt < 4; nt++)
#pragma unroll
                for (int q = 0; q < 4; q++) { mst[nt][q] += dH[nt][q]; dH[nt][q] = 0.f; }
        }
    }

    // ---- D -> hsum (alias stage-0 x buffer) ----
    float* hsum = x_s;
    __syncthreads();
#pragma unroll
    for (int nt = 0; nt < 4; nt++) {
        int col = nt * 8 + tg * 2;
#pragma unroll
        for (int q = 0; q < 4; q++) {
            float v = mst[nt][q] + dH[nt][q] + (dM[nt][q] + dL[nt][q]);
            int row = (q < 2) ? arow0 : arow0 + 8;
            hsum[row * HS + col + (q & 1)] = v;
        }
    }
    __syncthreads();

    // ---- epilogue: one thread per token ----
    if (tid < M_TILE) {
        const int t = tid;
        const int tok = tok0 + t;
        float g[NEXP], ctrl[NEXP], lg[NEXP], ln[NEXP], lo[NEXP];
#pragma unroll
        for (int e = 0; e < NEXP; e++) g[e] = tanhf(hsum[t * HS + e]);
#pragma unroll
        for (int e = 0; e < NEXP; e++) {
            float v = hsum[t * HS + NEXP + e];
            float sp = (v > 20.f) ? v : log1pf(__expf(v));
            ctrl[e] = sp + 0.01f;   // NOISE_EPS
        }
#pragma unroll
        for (int f = 0; f < NEXP; f++) {
            float s = 0.f;
#pragma unroll
            for (int e = 0; e < NEXP; e++) s = fmaf(g[e], w2_s[f * NEXP + e], s);
            lg[f] = s;
        }
        const float4* np = (const float4*)(noise + (size_t)tok * NEXP);
        float4 nz0 = np[0], nz1 = np[1], nz2 = np[2], nz3 = np[3];
        float nf[NEXP] = {nz0.x, nz0.y, nz0.z, nz0.w, nz1.x, nz1.y, nz1.z, nz1.w,
                          nz2.x, nz2.y, nz2.z, nz2.w, nz3.x, nz3.y, nz3.z, nz3.w};
#pragma unroll
        for (int f = 0; f < NEXP; f++) {
            ln[f] = nf[f] * ctrl[f];
            lo[f] = lg[f] + ln[f];
        }

        // top-5 (stable: ties keep smaller index)
        float tv[5]; int tix[5]; unsigned used = 0;
#pragma unroll
        for (int p = 0; p < 5; p++) {
            float best = -1e30f; int bi = 0;
#pragma unroll
            for (int f = 0; f < NEXP; f++) {
                bool ok = !((used >> f) & 1u) && (lo[f] > best);
                best = ok ? lo[f] : best;
                bi   = ok ? f     : bi;
            }
            used |= 1u << bi;
            tv[p] = best; tix[p] = bi;
        }

        float ex[NSEL], ssum = 0.f;
#pragma unroll
        for (int p = 0; p < NSEL; p++) { ex[p] = __expf(tv[p] - tv[0]); ssum += ex[p]; }
        float inv = 1.f / ssum;
#pragma unroll
        for (int p = 0; p < NSEL; p++) {
            float sc = ex[p] * inv;
            out[(size_t)tok * NSEL + p] = (float)tix[p];
            out[(size_t)N_TOKEN * NSEL + (size_t)tok * NSEL + p] = sc;
            atomicAdd(&imp_s[tix[p]], sc);
        }
        const float thr_in  = tv[4];
        const float thr_out = tv[3];
#pragma unroll
        for (int f = 0; f < NEXP; f++) {
            float thr = (ln[f] > thr_in) ? thr_in : thr_out;
            atomicAdd(&load_s[f], normcdff((lg[f] - thr) / ctrl[f]));
        }
    }
    __syncthreads();

    // ---- fused loss: global atomics, last block reduces ----
    if (tid < NEXP) {
        atomicAdd(&g_imp[tid],  imp_s[tid]);
        atomicAdd(&g_load[tid], load_s[tid]);
        __threadfence();
    }
    __syncthreads();
    if (tid == 0) s_last = (atomicAdd(&g_count, 1u) == NBLOCKS - 1);
    __syncthreads();
    if (s_last && tid == 0) {
        volatile float* vi = g_imp;
        volatile float* vl = g_load;
        double si = 0, sqi = 0, sl = 0, sql = 0;
        for (int e = 0; e < NEXP; e++) {
            double a = (double)vi[e]; si += a; sqi += a * a;
            double b = (double)vl[e]; sl += b; sql += b * b;
        }
        double mi = si / NEXP, ml = sl / NEXP;
        double viv = (sqi - si * si / NEXP) / (NEXP - 1);
        double vlv = (sql - sl * sl / NEXP) / (NEXP - 1);
        double cv = viv / (mi * mi + 1e-10) + vlv / (ml * ml + 1e-10);
        out[(size_t)2 * N_TOKEN * NSEL] = (float)(0.01 * cv);
        for (int e = 0; e < NEXP; e++) { g_imp[e] = 0.f; g_load[e] = 0.f; }
        g_count = 0;
    }
}

extern "C" void kernel_launch(void* const* d_in, const int* in_sizes, int n_in,
                              void* d_out, int out_size)
{
    const float* x     = (const float*)d_in[0];
    const float* w1    = (const float*)d_in[1];
    const float* w2    = (const float*)d_in[2];
    const float* wn    = (const float*)d_in[3];
    const float* noise = (const float*)d_in[4];
    float* out = (float*)d_out;

    wsplit_kernel<<<128, 256>>>(w1, wn);
    cudaFuncSetAttribute(gate_kernel,
                         cudaFuncAttributeMaxDynamicSharedMemorySize, DSMEM);
    gate_kernel<<<NBLOCKS, NTHREADS, DSMEM>>>(x, w2, noise, out);
}